// round 1
// baseline (speedup 1.0000x reference)
#include <cuda_runtime.h>
#include <math.h>

// Problem constants (fixed by the dataset)
#define FDIM 256
#define NB 8
#define NPATH 20
#define BM 32
#define BN 32
#define KT 16

// Scratch (device globals: allocation-free)
__device__ float g_Wc[FDIM * 64];   // per-feature 8x8 cayley-path coefficient matrix
__device__ float g_sig[FDIM * 4];   // sigmoid(a_norm)

// blade masks in CEGNN order: (), e0,e1,e2, e01,e02,e12, e012
__constant__ int c_masks[8] = {0, 1, 2, 4, 3, 5, 6, 7};
// path index lookup: (gi, gj, gk) -> p  (lexicographic argwhere order)
__constant__ int c_plut[64] = {
     0, -1, -1, -1,   -1,  1, -1, -1,   -1, -1,  2, -1,   -1, -1, -1,  3,
    -1,  4, -1, -1,    5, -1,  6, -1,   -1,  7, -1,  8,   -1, -1,  9, -1,
    -1, -1, 10, -1,   -1, 11, -1, 12,   13, -1, 14, -1,   -1, 15, -1, -1,
    -1, -1, -1, 16,   -1, -1, 17, -1,   -1, 18, -1, -1,   19, -1, -1, -1
};

// ---------------------------------------------------------------------------
// Prep kernel: Wc[n][i][k] = sign(m_i, m_k) * w_gp[n, path(g_i, g_j, g_k)]
// and g_sig[n][g] = sigmoid(a_norm[n][g]).  <<<FDIM, 64>>>
// ---------------------------------------------------------------------------
__global__ void sgp_prep(const float* __restrict__ w_gp,
                         const float* __restrict__ a_norm) {
    int n = blockIdx.x;
    int t = threadIdx.x;              // 64 threads: t = i*8 + k
    int i = t >> 3, k = t & 7;
    int mi = c_masks[i], mk = c_masks[k];
    int mj = mi ^ mk;
    int gi = __popc(mi), gj = __popc(mj), gk = __popc(mk);
    int p = c_plut[gi * 16 + gj * 4 + gk];
    // reordering sign (Euclidean metric, squares are +1)
    int s = 0, aa = mi >> 1;
    while (aa) { s += __popc(aa & mk); aa >>= 1; }
    float sgn = (s & 1) ? -1.0f : 1.0f;
    g_Wc[n * 64 + t] = sgn * w_gp[n * NPATH + p];
    if (t < 4) g_sig[n * 4 + t] = 1.0f / (1.0f + expf(-a_norm[n * 4 + t]));
}

// ---------------------------------------------------------------------------
// Main fused kernel: both grade-linears + normalize + geometric product +
// bias + 1/sqrt(2) scale, one pass, no intermediate global traffic for xr.
// Tile: BM=32 b-rows x BN=32 n-cols, 256 threads (16x16), micro-tile 2x2.
// ---------------------------------------------------------------------------
__global__ void __launch_bounds__(256)
sgp_main(const float* __restrict__ x,
         const float* __restrict__ wL,
         const float* __restrict__ bL,
         const float* __restrict__ wR,
         float* __restrict__ out) {
    __shared__ float xs[KT][BM * NB];    // xs[m][b*8 + i]
    __shared__ float wls[KT][BN * 4];    // wls[m][n*4 + g]
    __shared__ float wrs[KT][BN * 4];

    const int tid = threadIdx.x;
    const int tx = tid & 15;             // n-group 0..15
    const int ty = tid >> 4;             // b-group 0..15
    const int b0 = blockIdx.x * BM;
    const int n0 = blockIdx.y * BN;

    float accL[2][2][NB];
    float accR[2][2][NB];
#pragma unroll
    for (int a = 0; a < 2; a++)
#pragma unroll
        for (int c = 0; c < 2; c++)
#pragma unroll
            for (int i = 0; i < NB; i++) { accL[a][c][i] = 0.0f; accR[a][c][i] = 0.0f; }

    const int xbl = tid >> 3;            // 0..31: b row within tile
    const int xseg = tid & 7;            // 0..7 : 16-float segment within the 128-float k-row

    for (int kt = 0; kt < FDIM; kt += KT) {
        // --- load x tile: 32 b x 16 m x 8 blades (coalesced, 16 floats/thread)
        const float4* xsrc =
            (const float4*)(x + ((size_t)(b0 + xbl) * FDIM + kt) * NB + xseg * 16);
        float4 v0 = xsrc[0], v1 = xsrc[1], v2 = xsrc[2], v3 = xsrc[3];
        float4* d0 = (float4*)&xs[xseg * 2][xbl * NB];
        d0[0] = v0; d0[1] = v1;
        float4* d1 = (float4*)&xs[xseg * 2 + 1][xbl * NB];
        d1[0] = v2; d1[1] = v3;

        // --- load both weight tiles: 32 n x 16 m x 4 grades each
#pragma unroll
        for (int q = 0; q < 2; q++) {
            int u = tid * 2 + q;
            int nl = u >> 4, ml = u & 15;
            *(float4*)&wls[ml][nl * 4] =
                *(const float4*)(wL + ((size_t)(n0 + nl) * FDIM + kt + ml) * 4);
            *(float4*)&wrs[ml][nl * 4] =
                *(const float4*)(wR + ((size_t)(n0 + nl) * FDIM + kt + ml) * 4);
        }
        __syncthreads();

#pragma unroll
        for (int k = 0; k < KT; k++) {
            float xa[2][NB];
#pragma unroll
            for (int bb = 0; bb < 2; bb++) {
                const float4* px = (const float4*)&xs[k][(ty * 2 + bb) * NB];
                float4 a0 = px[0], a1 = px[1];
                xa[bb][0] = a0.x; xa[bb][1] = a0.y; xa[bb][2] = a0.z; xa[bb][3] = a0.w;
                xa[bb][4] = a1.x; xa[bb][5] = a1.y; xa[bb][6] = a1.z; xa[bb][7] = a1.w;
            }
#pragma unroll
            for (int nn = 0; nn < 2; nn++) {
                float4 wl = *(const float4*)&wls[k][(tx * 2 + nn) * 4];
                float4 wr = *(const float4*)&wrs[k][(tx * 2 + nn) * 4];
                // grade map [0,1,1,1,2,2,2,3] baked as register copies (folded)
                float wlg[NB] = {wl.x, wl.y, wl.y, wl.y, wl.z, wl.z, wl.z, wl.w};
                float wrg[NB] = {wr.x, wr.y, wr.y, wr.y, wr.z, wr.z, wr.z, wr.w};
#pragma unroll
                for (int bb = 0; bb < 2; bb++) {
#pragma unroll
                    for (int i = 0; i < NB; i++) {
                        accL[bb][nn][i] += xa[bb][i] * wlg[i];
                        accR[bb][nn][i] += xa[bb][i] * wrg[i];
                    }
                }
            }
        }
        __syncthreads();
    }

    // --- fused epilogue: normalize xr, geometric product, bias, scale, store
    // j(i,k) = idx[mask_i ^ mask_k], fully unrolled so gp[] stays in registers
    const int JT[64] = {
        0,1,2,3,4,5,6,7,
        1,0,4,5,2,3,7,6,
        2,4,0,6,1,7,3,5,
        3,5,6,0,7,1,2,4,
        4,2,1,7,0,6,5,3,
        5,3,7,1,6,0,4,2,
        6,7,3,2,5,4,0,1,
        7,6,5,4,3,2,1,0 };
    const float RS2 = 0.7071067811865476f;

#pragma unroll
    for (int bb = 0; bb < 2; bb++) {
#pragma unroll
        for (int nn = 0; nn < 2; nn++) {
            const int b = b0 + ty * 2 + bb;
            const int n = n0 + tx * 2 + nn;

            float qs[4];
            qs[0] = accR[bb][nn][0] * accR[bb][nn][0];
            qs[1] = accR[bb][nn][1] * accR[bb][nn][1]
                  + accR[bb][nn][2] * accR[bb][nn][2]
                  + accR[bb][nn][3] * accR[bb][nn][3];
            qs[2] = accR[bb][nn][4] * accR[bb][nn][4]
                  + accR[bb][nn][5] * accR[bb][nn][5]
                  + accR[bb][nn][6] * accR[bb][nn][6];
            qs[3] = accR[bb][nn][7] * accR[bb][nn][7];

            float inv[4];
#pragma unroll
            for (int g = 0; g < 4; g++) {
                float nm = sqrtf(sqrtf(qs[g] * qs[g] + 1e-16f));   // (q^2+1e-16)^0.25
                float sg = g_sig[n * 4 + g];
                inv[g] = 1.0f / (sg * (nm - 1.0f) + 1.0f + 1e-6f);
            }
            float xr[NB];
            xr[0] = accR[bb][nn][0] * inv[0];
            xr[1] = accR[bb][nn][1] * inv[1];
            xr[2] = accR[bb][nn][2] * inv[1];
            xr[3] = accR[bb][nn][3] * inv[1];
            xr[4] = accR[bb][nn][4] * inv[2];
            xr[5] = accR[bb][nn][5] * inv[2];
            xr[6] = accR[bb][nn][6] * inv[2];
            xr[7] = accR[bb][nn][7] * inv[3];

            // x at the OUTPUT feature index n (bilinear term)
            const float4* xp = (const float4*)(x + ((size_t)b * FDIM + n) * NB);
            float4 x0 = xp[0], x1 = xp[1];
            float xv[NB] = {x0.x, x0.y, x0.z, x0.w, x1.x, x1.y, x1.z, x1.w};

            const float* wc = g_Wc + n * 64;
            float gp[NB] = {0, 0, 0, 0, 0, 0, 0, 0};
#pragma unroll
            for (int i = 0; i < 8; i++) {
#pragma unroll
                for (int k = 0; k < 8; k++) {
                    gp[JT[i * 8 + k]] += wc[i * 8 + k] * xv[i] * xr[k];
                }
            }

            float o[NB];
#pragma unroll
            for (int i = 0; i < NB; i++)
                o[i] = (accL[bb][nn][i] + gp[i]) * RS2;
            o[0] += bL[n] * RS2;   // bias lives in the scalar blade, pre-scale

            float4* op = (float4*)(out + ((size_t)b * FDIM + n) * NB);
            op[0] = make_float4(o[0], o[1], o[2], o[3]);
            op[1] = make_float4(o[4], o[5], o[6], o[7]);
        }
    }
}

// ---------------------------------------------------------------------------
// inputs (metadata order): x, w_left, b_left, w_right, a_norm, w_gp
// ---------------------------------------------------------------------------
extern "C" void kernel_launch(void* const* d_in, const int* in_sizes, int n_in,
                              void* d_out, int out_size) {
    const float* x      = (const float*)d_in[0];
    const float* wL     = (const float*)d_in[1];
    const float* bLp    = (const float*)d_in[2];
    const float* wR     = (const float*)d_in[3];
    const float* a_norm = (const float*)d_in[4];
    const float* w_gp   = (const float*)d_in[5];
    float* out = (float*)d_out;

    int Bdim = in_sizes[0] / (FDIM * NB);   // 8192

    sgp_prep<<<FDIM, 64>>>(w_gp, a_norm);

    dim3 grid(Bdim / BM, FDIM / BN);
    sgp_main<<<grid, 256>>>(x, wL, bLp, wR, out);
}

// round 3
// speedup vs baseline: 5.2756x; 5.2756x over previous
#include <cuda_runtime.h>
#include <cstdint>
#include <math.h>

#define FDIM 256
#define NB 8
#define NPATH 20
#define BDIM 8192
#define NROWS (NB * BDIM)          // 65536 GEMM rows (plane-major)
#define KDIM FDIM                  // 256
#define GBM 128                    // CTA rows
#define GBN 64                     // CTA n-cols (per side; both sides computed)
#define KC 32                      // k per pipeline chunk
#define NCHUNK (KDIM / KC)         // 8
// smem: rows stride 144B (36 floats) -> conflict-free fragments, 16B aligned
#define ROWSTRIDE_F 36
#define A_ROWS 128
#define B_ROWS 128                 // 64 n x 2 sides
#define A_BYTES (A_ROWS * ROWSTRIDE_F * 4)   // 18432
#define B_BYTES (B_ROWS * ROWSTRIDE_F * 4)   // 18432
#define STAGE_BYTES (A_BYTES + B_BYTES)      // 36864
#define SMEM_TOTAL (2 * STAGE_BYTES)         // 73728

// ---------------- scratch (device globals: allocation-free) ----------------
__device__ float g_xt[(size_t)NROWS * KDIM];        // 64MB [row=i*8192+b][m] (tf32-rounded)
__device__ float g_L [(size_t)FDIM * NROWS];        // 64MB [n][row]
__device__ float g_R [(size_t)FDIM * NROWS];        // 64MB [n][row]
__device__ float g_wt[(size_t)2 * 4 * FDIM * FDIM]; // 2MB [side][grade][n][m] (tf32-rounded)
__device__ float g_Wc[FDIM * 64];
__device__ float g_sig[FDIM * 4];

__constant__ int c_masks[8] = {0, 1, 2, 4, 3, 5, 6, 7};
__constant__ int c_plut[64] = {
     0, -1, -1, -1,   -1,  1, -1, -1,   -1, -1,  2, -1,   -1, -1, -1,  3,
    -1,  4, -1, -1,    5, -1,  6, -1,   -1,  7, -1,  8,   -1, -1,  9, -1,
    -1, -1, 10, -1,   -1, 11, -1, 12,   13, -1, 14, -1,   -1, 15, -1, -1,
    -1, -1, -1, 16,   -1, -1, 17, -1,   -1, 18, -1, -1,   19, -1, -1, -1
};
__constant__ int c_grade_of_plane[8] = {0, 1, 1, 1, 2, 2, 2, 3};

// ---------------- helpers ----------------
__device__ __forceinline__ uint32_t to_tf32(float f) {
    uint32_t r;
    asm("cvt.rna.tf32.f32 %0, %1;" : "=r"(r) : "f"(f));
    return r;
}
__device__ __forceinline__ uint32_t smem_u32(const void* p) {
    uint32_t r;
    asm("{ .reg .u64 t; cvta.to.shared.u64 t, %1; cvt.u32.u64 %0, t; }" : "=r"(r) : "l"(p));
    return r;
}
__device__ __forceinline__ void cp16(uint32_t sdst, const void* gsrc) {
    asm volatile("cp.async.cg.shared.global [%0], [%1], 16;" :: "r"(sdst), "l"(gsrc));
}
__device__ __forceinline__ void cp_commit() { asm volatile("cp.async.commit_group;"); }
template <int N> __device__ __forceinline__ void cp_wait() {
    asm volatile("cp.async.wait_group %0;" :: "n"(N));
}
__device__ __forceinline__ void mma_tf32(float* c, const uint32_t* a, const uint32_t* b) {
    asm volatile(
        "mma.sync.aligned.m16n8k8.row.col.f32.tf32.tf32.f32 "
        "{%0,%1,%2,%3}, {%4,%5,%6,%7}, {%8,%9}, {%0,%1,%2,%3};"
        : "+f"(c[0]), "+f"(c[1]), "+f"(c[2]), "+f"(c[3])
        : "r"(a[0]), "r"(a[1]), "r"(a[2]), "r"(a[3]), "r"(b[0]), "r"(b[1]));
}

// ---------------------------------------------------------------------------
// prep: Wc[n][i][k] = sign(m_i,m_k) * w_gp[n, path], sig = sigmoid(a_norm)
// ---------------------------------------------------------------------------
__global__ void sgp_prep(const float* __restrict__ w_gp,
                         const float* __restrict__ a_norm) {
    int n = blockIdx.x;
    int t = threadIdx.x;
    int i = t >> 3, k = t & 7;
    int mi = c_masks[i], mk = c_masks[k];
    int gi = __popc(mi), gj = __popc(mi ^ mk), gk = __popc(mk);
    int p = c_plut[gi * 16 + gj * 4 + gk];
    int s = 0, aa = mi >> 1;
    while (aa) { s += __popc(aa & mk); aa >>= 1; }
    float sgn = (s & 1) ? -1.0f : 1.0f;
    g_Wc[n * 64 + t] = sgn * w_gp[n * NPATH + p];
    if (t < 4) g_sig[n * 4 + t] = 1.0f / (1.0f + expf(-a_norm[n * 4 + t]));
}

// ---------------------------------------------------------------------------
// weight gather + tf32 round: wt[side][g][n][m] = tf32(w_side[n][m][g])
// ---------------------------------------------------------------------------
__global__ void __launch_bounds__(256) sgp_wprep(const float* __restrict__ wL,
                                                 const float* __restrict__ wR) {
    int idx = blockIdx.x * 256 + threadIdx.x;   // over 4*256*256
    int m = idx & 255, n = (idx >> 8) & 255, g = idx >> 16;
    uint32_t vl = to_tf32(wL[((size_t)n * 256 + m) * 4 + g]);
    uint32_t vr = to_tf32(wR[((size_t)n * 256 + m) * 4 + g]);
    ((uint32_t*)g_wt)[((size_t)(0 * 4 + g) * 256 + n) * 256 + m] = vl;
    ((uint32_t*)g_wt)[((size_t)(1 * 4 + g) * 256 + n) * 256 + m] = vr;
}

// ---------------------------------------------------------------------------
// transpose + tf32 round: xt[i*8192+b][m] = tf32(x[b][m][i])
// ---------------------------------------------------------------------------
__global__ void __launch_bounds__(256) sgp_xt(const float* __restrict__ x) {
    int idx = blockIdx.x * 256 + threadIdx.x;   // over B*F = 2M (m fastest)
    int m = idx & 255, b = idx >> 8;
    const float4* p = (const float4*)(x + (size_t)idx * NB);
    float4 a = p[0], c = p[1];
    float v[8] = {a.x, a.y, a.z, a.w, c.x, c.y, c.z, c.w};
#pragma unroll
    for (int i = 0; i < 8; i++)
        ((uint32_t*)g_xt)[((size_t)i * BDIM + b) * KDIM + m] = to_tf32(v[i]);
}

// ---------------------------------------------------------------------------
// tf32 mma.sync GEMM: L[n][row] = xt[row,:]·wLg[n,:],  R likewise.
// CTA tile: 128 rows x 64 n x both sides. 8 warps (2m x 4n), warp 64x16x2.
// cp.async double-buffered K-chunks of 32.
// ---------------------------------------------------------------------------
__global__ void __launch_bounds__(256)
sgp_gemm() {
    extern __shared__ __align__(16) char sm[];

    const int tid = threadIdx.x;
    const int lane = tid & 31;
    const int wid = tid >> 5;
    const int gquad = lane >> 2;   // 0..7
    const int t4 = lane & 3;       // 0..3
    const int wm = wid >> 2;       // 0..1 -> m offset wm*64
    const int wn = wid & 3;        // 0..3 -> n offset wn*16

    const int n0 = blockIdx.x * GBN;       // n-tile fastest -> L2 reuse of A
    const int rt = blockIdx.y;
    const int r0 = rt * GBM;
    const int grade = c_grade_of_plane[rt >> 6];

    const float* Abase = g_xt + (size_t)r0 * KDIM;
    const float* B0base = g_wt + ((size_t)(0 * 4 + grade) * 256 + n0) * 256;
    const float* B1base = g_wt + ((size_t)(1 * 4 + grade) * 256 + n0) * 256;

    // per-thread cp.async plan: 8 ops of 16B. flat 0..1023 = A, 1024..2047 = B
    uint32_t sdst[8];
    const float* gsrc[8];
    const uint32_t smbase = smem_u32(sm);
#pragma unroll
    for (int q = 0; q < 8; q++) {
        int flat = q * 256 + tid;
        if (flat < 1024) {
            int row = flat >> 3, seg = flat & 7;
            sdst[q] = smbase + row * (ROWSTRIDE_F * 4) + seg * 16;
            gsrc[q] = Abase + (size_t)row * KDIM + seg * 4;
        } else {
            int f2 = flat - 1024;
            int side = f2 >> 9;                 // 0..1
            int nr = (f2 >> 3) & 63;            // 0..63
            int seg = f2 & 7;
            sdst[q] = smbase + A_BYTES + (side * 64 + nr) * (ROWSTRIDE_F * 4) + seg * 16;
            gsrc[q] = (side ? B1base : B0base) + (size_t)nr * 256 + seg * 4;
        }
    }

    float acc[4][2][2][4];
#pragma unroll
    for (int mt = 0; mt < 4; mt++)
#pragma unroll
        for (int nt = 0; nt < 2; nt++)
#pragma unroll
            for (int s = 0; s < 2; s++)
#pragma unroll
                for (int r = 0; r < 4; r++) acc[mt][nt][s][r] = 0.0f;

    // issue chunk 0 into buf 0
#pragma unroll
    for (int q = 0; q < 8; q++) cp16(sdst[q], gsrc[q]);
    cp_commit();

    for (int c = 0; c < NCHUNK; c++) {
        const int buf = c & 1;
        if (c < NCHUNK - 1) {
            const int nb = buf ^ 1;
#pragma unroll
            for (int q = 0; q < 8; q++)
                cp16(sdst[q] + nb * STAGE_BYTES, gsrc[q] + (c + 1) * KC);
            cp_commit();
            cp_wait<1>();
        } else {
            cp_wait<0>();
        }
        __syncthreads();

        const uint32_t* As = (const uint32_t*)(sm + buf * STAGE_BYTES);
        const uint32_t* Bs = (const uint32_t*)(sm + buf * STAGE_BYTES + A_BYTES);

#pragma unroll
        for (int ks = 0; ks < 4; ks++) {
            const int k0 = ks * 8;
            uint32_t a[4][4];
#pragma unroll
            for (int mt = 0; mt < 4; mt++) {
                int m = wm * 64 + mt * 16 + gquad;
                a[mt][0] = As[m * ROWSTRIDE_F + k0 + t4];
                a[mt][1] = As[(m + 8) * ROWSTRIDE_F + k0 + t4];
                a[mt][2] = As[m * ROWSTRIDE_F + k0 + t4 + 4];
                a[mt][3] = As[(m + 8) * ROWSTRIDE_F + k0 + t4 + 4];
            }
            uint32_t b[2][2][2];
#pragma unroll
            for (int s = 0; s < 2; s++)
#pragma unroll
                for (int nt = 0; nt < 2; nt++) {
                    int n = s * 64 + wn * 16 + nt * 8 + gquad;
                    b[s][nt][0] = Bs[n * ROWSTRIDE_F + k0 + t4];
                    b[s][nt][1] = Bs[n * ROWSTRIDE_F + k0 + t4 + 4];
                }
#pragma unroll
            for (int mt = 0; mt < 4; mt++)
#pragma unroll
                for (int nt = 0; nt < 2; nt++)
#pragma unroll
                    for (int s = 0; s < 2; s++)
                        mma_tf32(acc[mt][nt][s], a[mt], b[s][nt]);
        }
        __syncthreads();
    }

    // store: col-major [n][row]; each scalar group = full 32B sectors
#pragma unroll
    for (int s = 0; s < 2; s++) {
        float* Ob = s ? g_R : g_L;
#pragma unroll
        for (int mt = 0; mt < 4; mt++) {
#pragma unroll
            for (int nt = 0; nt < 2; nt++) {
                int row = r0 + wm * 64 + mt * 16 + gquad;
                int col = n0 + wn * 16 + nt * 8 + 2 * t4;
                Ob[(size_t)col * NROWS + row]           = acc[mt][nt][s][0];
                Ob[(size_t)(col + 1) * NROWS + row]     = acc[mt][nt][s][1];
                Ob[(size_t)col * NROWS + row + 8]       = acc[mt][nt][s][2];
                Ob[(size_t)(col + 1) * NROWS + row + 8] = acc[mt][nt][s][3];
            }
        }
    }
}

// ---------------------------------------------------------------------------
// epilogue: norm(R) -> xr, gp = x ⊗_Wc xr, out = (L + gp + bias)/sqrt(2)
// one warp = 32 consecutive b at a fixed n
// ---------------------------------------------------------------------------
__global__ void __launch_bounds__(256) sgp_epi(const float* __restrict__ x,
                                               const float* __restrict__ bL,
                                               float* __restrict__ out) {
    int wg = blockIdx.x * 8 + (threadIdx.x >> 5);
    int lane = threadIdx.x & 31;
    int n = wg & 255;
    int b = ((wg >> 8) << 5) + lane;

    float Lv[8], Rv[8];
#pragma unroll
    for (int i = 0; i < 8; i++) {
        size_t row = (size_t)i * BDIM + b;
        Lv[i] = g_L[(size_t)n * NROWS + row];
        Rv[i] = g_R[(size_t)n * NROWS + row];
    }
    const float4* xp = (const float4*)(x + ((size_t)b * FDIM + n) * NB);
    float4 x0 = xp[0], x1 = xp[1];
    float xv[8] = {x0.x, x0.y, x0.z, x0.w, x1.x, x1.y, x1.z, x1.w};

    float qs[4];
    qs[0] = Rv[0] * Rv[0];
    qs[1] = Rv[1] * Rv[1] + Rv[2] * Rv[2] + Rv[3] * Rv[3];
    qs[2] = Rv[4] * Rv[4] + Rv[5] * Rv[5] + Rv[6] * Rv[6];
    qs[3] = Rv[7] * Rv[7];
    float inv[4];
#pragma unroll
    for (int g = 0; g < 4; g++) {
        float nm = sqrtf(sqrtf(qs[g] * qs[g] + 1e-16f));
        float sg = g_sig[n * 4 + g];
        inv[g] = 1.0f / (sg * (nm - 1.0f) + 1.0f + 1e-6f);
    }
    float xr[8];
    xr[0] = Rv[0] * inv[0];
    xr[1] = Rv[1] * inv[1];  xr[2] = Rv[2] * inv[1];  xr[3] = Rv[3] * inv[1];
    xr[4] = Rv[4] * inv[2];  xr[5] = Rv[5] * inv[2];  xr[6] = Rv[6] * inv[2];
    xr[7] = Rv[7] * inv[3];

    const int JT[64] = {
        0,1,2,3,4,5,6,7,
        1,0,4,5,2,3,7,6,
        2,4,0,6,1,7,3,5,
        3,5,6,0,7,1,2,4,
        4,2,1,7,0,6,5,3,
        5,3,7,1,6,0,4,2,
        6,7,3,2,5,4,0,1,
        7,6,5,4,3,2,1,0 };
    const float* wc = g_Wc + n * 64;
    float gp[8] = {0, 0, 0, 0, 0, 0, 0, 0};
#pragma unroll
    for (int i = 0; i < 8; i++) {
#pragma unroll
        for (int k = 0; k < 8; k++)
            gp[JT[i * 8 + k]] += wc[i * 8 + k] * xv[i] * xr[k];
    }

    const float RS2 = 0.7071067811865476f;
    float o[8];
#pragma unroll
    for (int i = 0; i < 8; i++) o[i] = (Lv[i] + gp[i]) * RS2;
    o[0] += bL[n] * RS2;

    float4* op = (float4*)(out + ((size_t)b * FDIM + n) * NB);
    op[0] = make_float4(o[0], o[1], o[2], o[3]);
    op[1] = make_float4(o[4], o[5], o[6], o[7]);
}

// ---------------------------------------------------------------------------
// inputs: x, w_left, b_left, w_right, a_norm, w_gp
// ---------------------------------------------------------------------------
extern "C" void kernel_launch(void* const* d_in, const int* in_sizes, int n_in,
                              void* d_out, int out_size) {
    const float* x      = (const float*)d_in[0];
    const float* wL     = (const float*)d_in[1];
    const float* bLp    = (const float*)d_in[2];
    const float* wR     = (const float*)d_in[3];
    const float* a_norm = (const float*)d_in[4];
    const float* w_gp   = (const float*)d_in[5];
    float* out = (float*)d_out;

    sgp_prep<<<FDIM, 64>>>(w_gp, a_norm);
    sgp_wprep<<<(4 * FDIM * FDIM) / 256, 256>>>(wL, wR);
    sgp_xt<<<(BDIM * FDIM) / 256, 256>>>(x);

    cudaFuncSetAttribute(sgp_gemm, cudaFuncAttributeMaxDynamicSharedMemorySize,
                         SMEM_TOTAL);
    dim3 gg(FDIM / GBN, NROWS / GBM);   // n-tiles fastest for A reuse in L2
    sgp_gemm<<<gg, 256, SMEM_TOTAL>>>();

    sgp_epi<<<(BDIM * FDIM) / 256, 256>>>(x, bLp, out);
}